// round 14
// baseline (speedup 1.0000x reference)
#include <cuda_runtime.h>
#include <cuda_fp16.h>
#include <cstdint>

// ---------------- problem constants ----------------
#define DIMC  1024
#define NH    16
#define HD    64
#define SEQ   2048
#define BATCH 2
#define GK    1024
#define SCALE_Q 0.125f

// scratch (device globals; no runtime allocation)
__device__ __half g_xh[BATCH * SEQ * DIMC];      // x in fp16
__device__ __half g_wqkvh[3 * DIMC * DIMC];      // W_qkv fp16
__device__ __half g_wprojh[DIMC * DIMC];         // W_proj fp16
__device__ __half g_Q[BATCH * NH * SEQ * HD];    // [B,H,N,D] fp16, pre-scaled
__device__ __half g_K[BATCH * NH * SEQ * HD];
__device__ __half g_V[BATCH * NH * SEQ * HD];
__device__ __half g_Oh[BATCH * SEQ * DIMC];      // attention out [B,N,C] fp16

__device__ __forceinline__ uint32_t smem_u32(const void* p) {
    uint32_t a;
    asm("{ .reg .u64 t; cvta.to.shared.u64 t, %1; cvt.u32.u64 %0, t; }"
        : "=r"(a) : "l"(p));
    return a;
}

__device__ __forceinline__ uint32_t pack_h2(float lo, float hi) {
    __half2 h = __floats2half2_rn(lo, hi);
    return *(uint32_t*)&h;
}

__device__ __forceinline__ void mma_f16(float* c, const uint32_t* a, const uint32_t* b) {
    asm volatile(
        "mma.sync.aligned.m16n8k16.row.col.f32.f16.f16.f32 "
        "{%0,%1,%2,%3}, {%4,%5,%6,%7}, {%8,%9}, {%0,%1,%2,%3};"
        : "+f"(c[0]), "+f"(c[1]), "+f"(c[2]), "+f"(c[3])
        : "r"(a[0]), "r"(a[1]), "r"(a[2]), "r"(a[3]), "r"(b[0]), "r"(b[1]));
}

__device__ __forceinline__ void ldsm_x4(uint32_t* r, uint32_t addr) {
    asm volatile("ldmatrix.sync.aligned.m8n8.x4.shared.b16 {%0,%1,%2,%3}, [%4];"
        : "=r"(r[0]), "=r"(r[1]), "=r"(r[2]), "=r"(r[3]) : "r"(addr));
}

__device__ __forceinline__ void ldsm_x4_t(uint32_t* r, uint32_t addr) {
    asm volatile("ldmatrix.sync.aligned.m8n8.x4.trans.shared.b16 {%0,%1,%2,%3}, [%4];"
        : "=r"(r[0]), "=r"(r[1]), "=r"(r[2]), "=r"(r[3]) : "r"(addr));
}

__device__ __forceinline__ void cp16(uint32_t dst, const void* src) {
    asm volatile("cp.async.cg.shared.global [%0], [%1], 16;"
        :: "r"(dst), "l"(src));
}
#define CP_COMMIT() asm volatile("cp.async.commit_group;" ::: "memory")

// ============================================================================
// fp32 -> fp16 streaming convert (float4 -> half2x2 per thread)
// ============================================================================
__global__ __launch_bounds__(256) void f2h_kernel(
    const float4* __restrict__ in, uint2* __restrict__ out, int n4)
{
    int i = blockIdx.x * blockDim.x + threadIdx.x;
    if (i < n4) {
        float4 v = in[i];
        uint2 o;
        o.x = pack_h2(v.x, v.y);
        o.y = pack_h2(v.z, v.w);
        out[i] = o;
    }
}

// ============================================================================
// TN GEMM, fp16 inputs, fp32 acc: C[m,n] = sum_k A[m,k] * B[n,k].
// CTA tile 128x128, K-chunk 32 halfs, 3-stage cp.async pipeline.
// 256 threads = 8 warps (2 M x 4 N), warp 64x32; ldmatrix frag loads.
// mode 0: QKV scatter (fp16 out, Q scaled); mode 1: fp32 out + bias.
// ============================================================================
#define ALD 40                      // halfs per smem row (80B) -> LDSM conflict-free
#define STG (2 * 128 * ALD)         // halfs per stage (A + B)
#define GEMM_SMEM (3 * STG * 2)     // bytes, 3 stages

__global__ __launch_bounds__(256) void gemm_h_kernel(
    const __half* __restrict__ A, const __half* __restrict__ B, int mode,
    __half* __restrict__ Qb, __half* __restrict__ Kb, __half* __restrict__ Vb,
    const float* __restrict__ bias, float* __restrict__ Out)
{
    extern __shared__ __half smh[];
    const int tid = threadIdx.x, wid = tid >> 5, lane = tid & 31;
    const int n0 = blockIdx.x * 128, m0 = blockIdx.y * 128;
    const int wm = wid >> 2;
    const int wn = wid & 3;
    const int lr = lane >> 2, lc = lane & 3;
    const uint32_t sb = smem_u32(smh);

    // ldmatrix lane address components (half units)
    const int f_row = lane & 15;
    const int f_col = (lane >> 4) << 3;

    // cp.async fill mapping: per stage 1024 chunks (512 A + 512 B), 4/thread
    const int crow = tid >> 2;          // 0..63 (+64)
    const int cch  = (tid & 3) << 3;    // half offset 0,8,16,24

    const __half* Ag = A + (size_t)m0 * GK;
    const __half* Bg = B + (size_t)n0 * GK;

    float acc[4][4][4];
    #pragma unroll
    for (int mt = 0; mt < 4; mt++)
        #pragma unroll
        for (int nt = 0; nt < 4; nt++)
            #pragma unroll
            for (int j = 0; j < 4; j++) acc[mt][nt][j] = 0.f;

    const int NCHUNK = GK / 32;         // 32

    // issue stage s <- chunk kt
    #define G_ISSUE(s, kt) do {                                                  \
        uint32_t ab = sb + (uint32_t)(s) * STG * 2;                              \
        uint32_t bb = ab + 128 * ALD * 2;                                        \
        _Pragma("unroll")                                                        \
        for (int i_ = 0; i_ < 2; i_++) {                                         \
            int row_ = crow + i_ * 64;                                           \
            cp16(ab + (uint32_t)((row_ * ALD + cch) * 2),                        \
                 Ag + (size_t)row_ * GK + (kt) * 32 + cch);                      \
            cp16(bb + (uint32_t)((row_ * ALD + cch) * 2),                        \
                 Bg + (size_t)row_ * GK + (kt) * 32 + cch);                      \
        }                                                                        \
        CP_COMMIT();                                                             \
    } while (0)

    G_ISSUE(0, 0);
    G_ISSUE(1, 1);

    for (int kt = 0; kt < NCHUNK; kt++) {
        if (kt + 2 < NCHUNK) {
            G_ISSUE((kt + 2) % 3, kt + 2);
            asm volatile("cp.async.wait_group 2;" ::: "memory");
        } else if (kt + 1 < NCHUNK) {
            asm volatile("cp.async.wait_group 1;" ::: "memory");
        } else {
            asm volatile("cp.async.wait_group 0;" ::: "memory");
        }
        __syncthreads();

        const uint32_t abase = sb + (uint32_t)((kt % 3) * STG) * 2u;
        const uint32_t bbase = abase + 128 * ALD * 2;
        #pragma unroll
        for (int ks = 0; ks < 2; ks++) {
            uint32_t afr[4][4], bfr[2][4];
            #pragma unroll
            for (int mt = 0; mt < 4; mt++)
                ldsm_x4(afr[mt],
                        abase + (uint32_t)(((wm * 64 + mt * 16 + f_row) * ALD
                                            + ks * 16 + f_col) * 2));
            #pragma unroll
            for (int p = 0; p < 2; p++)
                ldsm_x4(bfr[p],
                        bbase + (uint32_t)(((wn * 32 + p * 16 + f_row) * ALD
                                            + ks * 16 + f_col) * 2));
            #pragma unroll
            for (int mt = 0; mt < 4; mt++)
                #pragma unroll
                for (int nt = 0; nt < 4; nt++) {
                    uint32_t b2[2] = { bfr[nt >> 1][nt & 1], bfr[nt >> 1][2 + (nt & 1)] };
                    mma_f16(acc[mt][nt], afr[mt], b2);
                }
        }
        __syncthreads();
    }
    #undef G_ISSUE

    #pragma unroll
    for (int mt = 0; mt < 4; mt++) {
        #pragma unroll
        for (int nt = 0; nt < 4; nt++) {
            #pragma unroll
            for (int half_ = 0; half_ < 2; half_++) {
                int row = m0 + wm * 64 + mt * 16 + lr + half_ * 8;
                int col = n0 + wn * 32 + nt * 8 + lc * 2;
                float vx = acc[mt][nt][half_ * 2 + 0];
                float vy = acc[mt][nt][half_ * 2 + 1];
                if (mode == 0) {
                    int b = row >> 11, n = row & 2047;
                    int t = col >> 10, h = (col >> 6) & 15, d = col & 63;
                    size_t dst = ((size_t)((b << 4) + h) * SEQ + n) * HD + d;
                    if (t == 0)
                        *(uint32_t*)(Qb + dst) = pack_h2(vx * SCALE_Q, vy * SCALE_Q);
                    else if (t == 1)
                        *(uint32_t*)(Kb + dst) = pack_h2(vx, vy);
                    else
                        *(uint32_t*)(Vb + dst) = pack_h2(vx, vy);
                } else {
                    float2 bb = *(const float2*)(bias + col);
                    float2 v; v.x = vx + bb.x; v.y = vy + bb.y;
                    *(float2*)(Out + (size_t)row * DIMC + col) = v;
                }
            }
        }
    }
}

// ============================================================================
// Flash attention via mma.sync f16 (k16) + ldmatrix; cp.async double-buffered
// fp16 K/V tiles (validated R10). Output written fp16 [B,N,C].
// CTA: 128 q-rows of one (b,h); 8 warps x 16 rows. KV tile 64.
// ============================================================================
#define QT 128
#define KT 64
#define TLD 72
#define KBUF (KT * TLD)
#define AT_SMEM ((4 * KBUF + QT * TLD) * 2)

__global__ __launch_bounds__(256) void attn_mma_kernel(
    const __half* __restrict__ Qb, const __half* __restrict__ Kb,
    const __half* __restrict__ Vb, __half* __restrict__ Ob)
{
    extern __shared__ __half smh[];
    __half* Ks0 = smh;
    __half* Vs0 = Ks0 + 2 * KBUF;
    __half* Ps  = Vs0 + 2 * KBUF;

    const int tid = threadIdx.x, wid = tid >> 5, lane = tid & 31;
    const int lr = lane >> 2, lc = lane & 3;
    const int bh = blockIdx.y;
    const int q0 = blockIdx.x * QT;
    const __half* Qp = Qb + (size_t)bh * SEQ * HD;
    const __half* Kp = Kb + (size_t)bh * SEQ * HD;
    const __half* Vp = Vb + (size_t)bh * SEQ * HD;

    const int a_row  = lane & 15;
    const int a_col  = (lane >> 4) << 3;
    const int s_row  = lane & 7;
    const int s_col  = (lane >> 3) << 3;

    const uint32_t ksb[2] = { smem_u32(Ks0), smem_u32(Ks0 + KBUF) };
    const uint32_t vsb[2] = { smem_u32(Vs0), smem_u32(Vs0 + KBUF) };

    const int crow = tid >> 3;
    const int cch  = (tid & 7) << 3;

    #pragma unroll
    for (int i = 0; i < 2; i++) {
        int row = crow + i * 32;
        cp16(ksb[0] + (uint32_t)((row * TLD + cch) * 2), Kp + (size_t)row * HD + cch);
        cp16(vsb[0] + (uint32_t)((row * TLD + cch) * 2), Vp + (size_t)row * HD + cch);
    }
    CP_COMMIT();

    #pragma unroll
    for (int i = 0; i < 4; i++) {
        int f = tid + i * 256;
        int row = f >> 3, ch = (f & 7) << 3;
        *(uint4*)&Ps[row * TLD + ch] = *(const uint4*)&Qp[(size_t)(q0 + row) * HD + ch];
    }
    __syncthreads();

    uint32_t qf[4][4];
    {
        const uint32_t qwb = smem_u32(Ps + (wid * 16) * TLD);
        #pragma unroll
        for (int ks = 0; ks < 4; ks++)
            ldsm_x4(qf[ks], qwb + (uint32_t)((a_row * TLD + ks * 16 + a_col) * 2));
    }

    float m_run[2] = { -1e30f, -1e30f };
    float l_run[2] = { 0.f, 0.f };
    float oacc[8][4];
    #pragma unroll
    for (int nt = 0; nt < 8; nt++)
        #pragma unroll
        for (int j = 0; j < 4; j++) oacc[nt][j] = 0.f;

    __half* Pw = Ps + (wid * 16) * TLD;
    const uint32_t pwb = smem_u32(Pw);

    const int NT = SEQ / KT;
    for (int t = 0; t < NT; t++) {
        const int buf = t & 1;
        if (t + 1 < NT) {
            const int c1 = (t + 1) * KT;
            const int nb = buf ^ 1;
            #pragma unroll
            for (int i = 0; i < 2; i++) {
                int row = crow + i * 32;
                cp16(ksb[nb] + (uint32_t)((row * TLD + cch) * 2),
                     Kp + (size_t)(c1 + row) * HD + cch);
                cp16(vsb[nb] + (uint32_t)((row * TLD + cch) * 2),
                     Vp + (size_t)(c1 + row) * HD + cch);
            }
            CP_COMMIT();
            asm volatile("cp.async.wait_group 1;" ::: "memory");
        } else {
            asm volatile("cp.async.wait_group 0;" ::: "memory");
        }
        __syncthreads();

        const uint32_t kcur = ksb[buf];
        const uint32_t vcur = vsb[buf];

        float sacc[8][4];
        #pragma unroll
        for (int nt = 0; nt < 8; nt++)
            #pragma unroll
            for (int j = 0; j < 4; j++) sacc[nt][j] = 0.f;

        #pragma unroll
        for (int nt = 0; nt < 8; nt++) {
            #pragma unroll
            for (int ks = 0; ks < 2; ks++) {
                uint32_t kb[4];
                ldsm_x4(kb, kcur + (uint32_t)(((nt * 8 + s_row) * TLD
                                               + ks * 32 + s_col) * 2));
                mma_f16(sacc[nt], qf[2 * ks],     kb);
                mma_f16(sacc[nt], qf[2 * ks + 1], kb + 2);
            }
        }

        #pragma unroll
        for (int x = 0; x < 2; x++) {
            float mt = -1e30f;
            #pragma unroll
            for (int nt = 0; nt < 8; nt++)
                mt = fmaxf(mt, fmaxf(sacc[nt][2 * x], sacc[nt][2 * x + 1]));
            mt = fmaxf(mt, __shfl_xor_sync(0xffffffffu, mt, 1, 4));
            mt = fmaxf(mt, __shfl_xor_sync(0xffffffffu, mt, 2, 4));
            float m_new = fmaxf(m_run[x], mt);
            float alpha = __expf(m_run[x] - m_new);
            float lsum = 0.f;
            #pragma unroll
            for (int nt = 0; nt < 8; nt++) {
                float p0 = __expf(sacc[nt][2 * x]     - m_new);
                float p1 = __expf(sacc[nt][2 * x + 1] - m_new);
                sacc[nt][2 * x] = p0; sacc[nt][2 * x + 1] = p1;
                lsum += p0 + p1;
            }
            lsum += __shfl_xor_sync(0xffffffffu, lsum, 1, 4);
            lsum += __shfl_xor_sync(0xffffffffu, lsum, 2, 4);
            l_run[x] = l_run[x] * alpha + lsum;
            m_run[x] = m_new;
            #pragma unroll
            for (int nt = 0; nt < 8; nt++) {
                oacc[nt][2 * x]     *= alpha;
                oacc[nt][2 * x + 1] *= alpha;
            }
        }

        #pragma unroll
        for (int nt = 0; nt < 8; nt++) {
            *(uint32_t*)&Pw[lr * TLD + nt * 8 + 2 * lc]       = pack_h2(sacc[nt][0], sacc[nt][1]);
            *(uint32_t*)&Pw[(lr + 8) * TLD + nt * 8 + 2 * lc] = pack_h2(sacc[nt][2], sacc[nt][3]);
        }
        __syncwarp();

        #pragma unroll
        for (int kcp = 0; kcp < 4; kcp++) {
            uint32_t a[4];
            ldsm_x4(a, pwb + (uint32_t)((a_row * TLD + kcp * 16 + a_col) * 2));
            #pragma unroll
            for (int dp = 0; dp < 4; dp++) {
                uint32_t vb[4];
                ldsm_x4_t(vb, vcur + (uint32_t)(((kcp * 16 + a_row) * TLD
                                                 + dp * 16 + a_col) * 2));
                mma_f16(oacc[2 * dp],     a, vb);
                mma_f16(oacc[2 * dp + 1], a, vb + 2);
            }
        }
        __syncthreads();
    }

    // ---- finalize; write O fp16 in [B,N,C] layout ----
    const int b = bh >> 4, h = bh & 15;
    #pragma unroll
    for (int x = 0; x < 2; x++) {
        float inv = 1.f / l_run[x];
        int row = q0 + wid * 16 + lr + x * 8;
        __half* dst = Ob + ((size_t)(b * SEQ + row)) * DIMC + h * HD;
        #pragma unroll
        for (int nt = 0; nt < 8; nt++)
            *(uint32_t*)&dst[nt * 8 + 2 * lc] =
                pack_h2(oacc[nt][2 * x] * inv, oacc[nt][2 * x + 1] * inv);
    }
}

// ============================================================================
// Launcher
// ============================================================================
extern "C" void kernel_launch(void* const* d_in, const int* in_sizes, int n_in,
                              void* d_out, int out_size)
{
    const float* x     = (const float*)d_in[0];   // [2,2048,1024]
    const float* Wqkv  = (const float*)d_in[1];   // [3072,1024]
    const float* Wproj = (const float*)d_in[2];   // [1024,1024]
    const float* bproj = (const float*)d_in[3];   // [1024]
    float* out = (float*)d_out;

    __half *xh, *wqkvh, *wprojh, *Qb, *Kb, *Vb, *Oh;
    cudaGetSymbolAddress((void**)&xh,     g_xh);
    cudaGetSymbolAddress((void**)&wqkvh,  g_wqkvh);
    cudaGetSymbolAddress((void**)&wprojh, g_wprojh);
    cudaGetSymbolAddress((void**)&Qb, g_Q);
    cudaGetSymbolAddress((void**)&Kb, g_K);
    cudaGetSymbolAddress((void**)&Vb, g_V);
    cudaGetSymbolAddress((void**)&Oh, g_Oh);

    cudaFuncSetAttribute(gemm_h_kernel,
                         cudaFuncAttributeMaxDynamicSharedMemorySize, GEMM_SMEM);
    cudaFuncSetAttribute(attn_mma_kernel,
                         cudaFuncAttributeMaxDynamicSharedMemorySize, AT_SMEM);

    // 0) fp32 -> fp16 input conversion
    {
        int n4x = BATCH * SEQ * DIMC / 4;          // 1048576
        int n4q = 3 * DIMC * DIMC / 4;             // 786432
        int n4p = DIMC * DIMC / 4;                 // 262144
        f2h_kernel<<<n4x / 256, 256>>>((const float4*)x,     (uint2*)xh,     n4x);
        f2h_kernel<<<n4q / 256, 256>>>((const float4*)Wqkv,  (uint2*)wqkvh,  n4q);
        f2h_kernel<<<n4p / 256, 256>>>((const float4*)Wproj, (uint2*)wprojh, n4p);
    }

    // 1) QKV projection (fp16 in/out, fp32 acc); Q/K/V scatter
    dim3 g1(3 * DIMC / 128, (BATCH * SEQ) / 128);   // (24, 32)
    gemm_h_kernel<<<g1, 256, GEMM_SMEM>>>(xh, wqkvh, 0, Qb, Kb, Vb, nullptr, nullptr);

    // 2) flash attention (f16 mma) -> fp16 O
    dim3 g2(SEQ / QT, BATCH * NH);                  // (16, 32)
    attn_mma_kernel<<<g2, 256, AT_SMEM>>>(Qb, Kb, Vb, Oh);

    // 3) output projection (fp16 in, fp32 out) + bias
    dim3 g3(DIMC / 128, (BATCH * SEQ) / 128);       // (8, 32)
    gemm_h_kernel<<<g3, 256, GEMM_SMEM>>>(Oh, wprojh, 1, nullptr, nullptr, nullptr,
                                          bproj, out);
}

// round 15
// speedup vs baseline: 1.0639x; 1.0639x over previous
#include <cuda_runtime.h>
#include <cuda_fp16.h>
#include <cstdint>

// ---------------- problem constants ----------------
#define DIMC  1024
#define NH    16
#define HD    64
#define SEQ   2048
#define BATCH 2
#define GK    1024
#define SCALE_Q 0.125f
#define QSCALE_L2E 0.180336880f     // SCALE_Q * log2(e)

// scratch (device globals; no runtime allocation)
__device__ __half g_xh[BATCH * SEQ * DIMC];      // x in fp16
__device__ __half g_wqkvh[3 * DIMC * DIMC];      // W_qkv fp16
__device__ __half g_wprojh[DIMC * DIMC];         // W_proj fp16
__device__ __half g_Q[BATCH * NH * SEQ * HD];    // [B,H,N,D] fp16, scaled by SCALE_Q*log2e
__device__ __half g_K[BATCH * NH * SEQ * HD];
__device__ __half g_V[BATCH * NH * SEQ * HD];
__device__ __half g_Oh[BATCH * SEQ * DIMC];      // attention out [B,N,C] fp16

__device__ __forceinline__ uint32_t smem_u32(const void* p) {
    uint32_t a;
    asm("{ .reg .u64 t; cvta.to.shared.u64 t, %1; cvt.u32.u64 %0, t; }"
        : "=r"(a) : "l"(p));
    return a;
}

__device__ __forceinline__ uint32_t pack_h2(float lo, float hi) {
    __half2 h = __floats2half2_rn(lo, hi);
    return *(uint32_t*)&h;
}

__device__ __forceinline__ float ex2(float x) {
    float y;
    asm("ex2.approx.f32 %0, %1;" : "=f"(y) : "f"(x));
    return y;
}

__device__ __forceinline__ void mma_f16(float* c, const uint32_t* a, const uint32_t* b) {
    asm volatile(
        "mma.sync.aligned.m16n8k16.row.col.f32.f16.f16.f32 "
        "{%0,%1,%2,%3}, {%4,%5,%6,%7}, {%8,%9}, {%0,%1,%2,%3};"
        : "+f"(c[0]), "+f"(c[1]), "+f"(c[2]), "+f"(c[3])
        : "r"(a[0]), "r"(a[1]), "r"(a[2]), "r"(a[3]), "r"(b[0]), "r"(b[1]));
}

__device__ __forceinline__ void ldsm_x4(uint32_t* r, uint32_t addr) {
    asm volatile("ldmatrix.sync.aligned.m8n8.x4.shared.b16 {%0,%1,%2,%3}, [%4];"
        : "=r"(r[0]), "=r"(r[1]), "=r"(r[2]), "=r"(r[3]) : "r"(addr));
}

__device__ __forceinline__ void ldsm_x4_t(uint32_t* r, uint32_t addr) {
    asm volatile("ldmatrix.sync.aligned.m8n8.x4.trans.shared.b16 {%0,%1,%2,%3}, [%4];"
        : "=r"(r[0]), "=r"(r[1]), "=r"(r[2]), "=r"(r[3]) : "r"(addr));
}

__device__ __forceinline__ void cp16(uint32_t dst, const void* src) {
    asm volatile("cp.async.cg.shared.global [%0], [%1], 16;"
        :: "r"(dst), "l"(src));
}
#define CP_COMMIT() asm volatile("cp.async.commit_group;" ::: "memory")

// ============================================================================
// fp32 -> fp16 streaming convert
// ============================================================================
__global__ __launch_bounds__(256) void f2h_kernel(
    const float4* __restrict__ in, uint2* __restrict__ out, int n4)
{
    int i = blockIdx.x * blockDim.x + threadIdx.x;
    if (i < n4) {
        float4 v = in[i];
        uint2 o;
        o.x = pack_h2(v.x, v.y);
        o.y = pack_h2(v.z, v.w);
        out[i] = o;
    }
}

// ============================================================================
// TN GEMM, fp16 inputs, fp32 acc. CTA tile 128x128, K-chunk 32 halfs,
// 3-stage cp.async pipeline, ONE __syncthreads per chunk:
//   wait(chunk kt) -> sync -> issue chunk kt+2 (into stage of kt-1) -> compute.
// Safe: all warps passed compute(kt-1) to reach the sync.
// ============================================================================
#define ALD 40
#define STG (2 * 128 * ALD)
#define GEMM_SMEM (3 * STG * 2)

__global__ __launch_bounds__(256) void gemm_h_kernel(
    const __half* __restrict__ A, const __half* __restrict__ B, int mode,
    __half* __restrict__ Qb, __half* __restrict__ Kb, __half* __restrict__ Vb,
    const float* __restrict__ bias, float* __restrict__ Out)
{
    extern __shared__ __half smh[];
    const int tid = threadIdx.x, wid = tid >> 5, lane = tid & 31;
    const int n0 = blockIdx.x * 128, m0 = blockIdx.y * 128;
    const int wm = wid >> 2;
    const int wn = wid & 3;
    const int lr = lane >> 2, lc = lane & 3;
    const uint32_t sb = smem_u32(smh);

    const int f_row = lane & 15;
    const int f_col = (lane >> 4) << 3;

    const int crow = tid >> 2;          // 0..63 (+64)
    const int cch  = (tid & 3) << 3;    // half offset 0,8,16,24

    const __half* Ag = A + (size_t)m0 * GK;
    const __half* Bg = B + (size_t)n0 * GK;

    float acc[4][4][4];
    #pragma unroll
    for (int mt = 0; mt < 4; mt++)
        #pragma unroll
        for (int nt = 0; nt < 4; nt++)
            #pragma unroll
            for (int j = 0; j < 4; j++) acc[mt][nt][j] = 0.f;

    const int NCHUNK = GK / 32;         // 32

    // issue chunk c into stage c%3
    #define G_ISSUE(c) do {                                                      \
        uint32_t ab = sb + (uint32_t)((c) % 3) * STG * 2;                        \
        uint32_t bb = ab + 128 * ALD * 2;                                        \
        _Pragma("unroll")                                                        \
        for (int i_ = 0; i_ < 2; i_++) {                                         \
            int row_ = crow + i_ * 64;                                           \
            cp16(ab + (uint32_t)((row_ * ALD + cch) * 2),                        \
                 Ag + (size_t)row_ * GK + (c) * 32 + cch);                       \
            cp16(bb + (uint32_t)((row_ * ALD + cch) * 2),                        \
                 Bg + (size_t)row_ * GK + (c) * 32 + cch);                       \
        }                                                                        \
        CP_COMMIT();                                                             \
    } while (0)

    G_ISSUE(0);
    G_ISSUE(1);

    for (int kt = 0; kt < NCHUNK; kt++) {
        if (kt + 1 < NCHUNK)
            asm volatile("cp.async.wait_group 1;" ::: "memory");
        else
            asm volatile("cp.async.wait_group 0;" ::: "memory");
        __syncthreads();
        if (kt + 2 < NCHUNK) G_ISSUE(kt + 2);   // overwrites stage of kt-1: safe

        const uint32_t abase = sb + (uint32_t)((kt % 3) * STG) * 2u;
        const uint32_t bbase = abase + 128 * ALD * 2;
        #pragma unroll
        for (int ks = 0; ks < 2; ks++) {
            uint32_t afr[4][4], bfr[2][4];
            #pragma unroll
            for (int mt = 0; mt < 4; mt++)
                ldsm_x4(afr[mt],
                        abase + (uint32_t)(((wm * 64 + mt * 16 + f_row) * ALD
                                            + ks * 16 + f_col) * 2));
            #pragma unroll
            for (int p = 0; p < 2; p++)
                ldsm_x4(bfr[p],
                        bbase + (uint32_t)(((wn * 32 + p * 16 + f_row) * ALD
                                            + ks * 16 + f_col) * 2));
            #pragma unroll
            for (int mt = 0; mt < 4; mt++)
                #pragma unroll
                for (int nt = 0; nt < 4; nt++) {
                    uint32_t b2[2] = { bfr[nt >> 1][nt & 1], bfr[nt >> 1][2 + (nt & 1)] };
                    mma_f16(acc[mt][nt], afr[mt], b2);
                }
        }
    }
    #undef G_ISSUE

    #pragma unroll
    for (int mt = 0; mt < 4; mt++) {
        #pragma unroll
        for (int nt = 0; nt < 4; nt++) {
            #pragma unroll
            for (int half_ = 0; half_ < 2; half_++) {
                int row = m0 + wm * 64 + mt * 16 + lr + half_ * 8;
                int col = n0 + wn * 32 + nt * 8 + lc * 2;
                float vx = acc[mt][nt][half_ * 2 + 0];
                float vy = acc[mt][nt][half_ * 2 + 1];
                if (mode == 0) {
                    int b = row >> 11, n = row & 2047;
                    int t = col >> 10, h = (col >> 6) & 15, d = col & 63;
                    size_t dst = ((size_t)((b << 4) + h) * SEQ + n) * HD + d;
                    if (t == 0)     // fold log2(e) into Q so softmax can use ex2
                        *(uint32_t*)(Qb + dst) = pack_h2(vx * QSCALE_L2E, vy * QSCALE_L2E);
                    else if (t == 1)
                        *(uint32_t*)(Kb + dst) = pack_h2(vx, vy);
                    else
                        *(uint32_t*)(Vb + dst) = pack_h2(vx, vy);
                } else {
                    float2 bb = *(const float2*)(bias + col);
                    float2 v; v.x = vx + bb.x; v.y = vy + bb.y;
                    *(float2*)(Out + (size_t)row * DIMC + col) = v;
                }
            }
        }
    }
}

// ============================================================================
// Flash attention, f16 mma + ldmatrix; 3-stage cp.async K/V pipeline with ONE
// __syncthreads per tile (same reordering proof as the GEMM). Softmax in
// log2-units (Q pre-scaled) -> bare ex2.approx. O written fp16 [B,N,C].
// CTA: 128 q-rows of one (b,h); 8 warps x 16 rows. KV tile 64.
// ============================================================================
#define QT 128
#define KT 64
#define TLD 72
#define KBUF (KT * TLD)             // halfs per matrix per stage
#define KVSTG (2 * KBUF)            // K+V per stage
#define AT_SMEM ((3 * KVSTG + QT * TLD) * 2)

__global__ __launch_bounds__(256) void attn_mma_kernel(
    const __half* __restrict__ Qb, const __half* __restrict__ Kb,
    const __half* __restrict__ Vb, __half* __restrict__ Ob)
{
    extern __shared__ __half smh[];
    __half* Ps = smh + 3 * KVSTG;           // Q staging, then P strips

    const int tid = threadIdx.x, wid = tid >> 5, lane = tid & 31;
    const int lr = lane >> 2, lc = lane & 3;
    const int bh = blockIdx.y;
    const int q0 = blockIdx.x * QT;
    const __half* Qp = Qb + (size_t)bh * SEQ * HD;
    const __half* Kp = Kb + (size_t)bh * SEQ * HD;
    const __half* Vp = Vb + (size_t)bh * SEQ * HD;

    const int a_row  = lane & 15;
    const int a_col  = (lane >> 4) << 3;
    const int s_row  = lane & 7;
    const int s_col  = (lane >> 3) << 3;

    const uint32_t sb = smem_u32(smh);

    const int crow = tid >> 3;               // 0..31 (+32)
    const int cch  = (tid & 7) << 3;

    // issue KV tile c into stage c%3
    #define A_ISSUE(c) do {                                                      \
        uint32_t kb_ = sb + (uint32_t)((c) % 3) * KVSTG * 2;                     \
        uint32_t vb_ = kb_ + KBUF * 2;                                           \
        _Pragma("unroll")                                                        \
        for (int i_ = 0; i_ < 2; i_++) {                                         \
            int row_ = crow + i_ * 32;                                           \
            cp16(kb_ + (uint32_t)((row_ * TLD + cch) * 2),                       \
                 Kp + (size_t)((c) * KT + row_) * HD + cch);                     \
            cp16(vb_ + (uint32_t)((row_ * TLD + cch) * 2),                       \
                 Vp + (size_t)((c) * KT + row_) * HD + cch);                     \
        }                                                                        \
        CP_COMMIT();                                                             \
    } while (0)

    A_ISSUE(0);
    A_ISSUE(1);

    // ---- stage Q (fp16, coalesced 16B copies) ----
    #pragma unroll
    for (int i = 0; i < 4; i++) {
        int f = tid + i * 256;
        int row = f >> 3, ch = (f & 7) << 3;
        *(uint4*)&Ps[row * TLD + ch] = *(const uint4*)&Qp[(size_t)(q0 + row) * HD + ch];
    }
    __syncthreads();

    uint32_t qf[4][4];
    {
        const uint32_t qwb = smem_u32(Ps + (wid * 16) * TLD);
        #pragma unroll
        for (int ks = 0; ks < 4; ks++)
            ldsm_x4(qf[ks], qwb + (uint32_t)((a_row * TLD + ks * 16 + a_col) * 2));
    }

    float m_run[2] = { -1e30f, -1e30f };
    float l_run[2] = { 0.f, 0.f };
    float oacc[8][4];
    #pragma unroll
    for (int nt = 0; nt < 8; nt++)
        #pragma unroll
        for (int j = 0; j < 4; j++) oacc[nt][j] = 0.f;

    __half* Pw = Ps + (wid * 16) * TLD;
    const uint32_t pwb = smem_u32(Pw);

    const int NT = SEQ / KT;        // 32
    for (int t = 0; t < NT; t++) {
        if (t + 1 < NT)
            asm volatile("cp.async.wait_group 1;" ::: "memory");
        else
            asm volatile("cp.async.wait_group 0;" ::: "memory");
        __syncthreads();
        if (t + 2 < NT) A_ISSUE(t + 2);      // overwrites stage of t-1: safe

        const uint32_t kcur = sb + (uint32_t)((t % 3) * KVSTG) * 2u;
        const uint32_t vcur = kcur + KBUF * 2;

        // ---- S = Q K^T ----
        float sacc[8][4];
        #pragma unroll
        for (int nt = 0; nt < 8; nt++)
            #pragma unroll
            for (int j = 0; j < 4; j++) sacc[nt][j] = 0.f;

        #pragma unroll
        for (int nt = 0; nt < 8; nt++) {
            #pragma unroll
            for (int ks = 0; ks < 2; ks++) {
                uint32_t kb[4];
                ldsm_x4(kb, kcur + (uint32_t)(((nt * 8 + s_row) * TLD
                                               + ks * 32 + s_col) * 2));
                mma_f16(sacc[nt], qf[2 * ks],     kb);
                mma_f16(sacc[nt], qf[2 * ks + 1], kb + 2);
            }
        }

        // ---- online softmax in log2-units (ex2 only) ----
        #pragma unroll
        for (int x = 0; x < 2; x++) {
            float mt = -1e30f;
            #pragma unroll
            for (int nt = 0; nt < 8; nt++)
                mt = fmaxf(mt, fmaxf(sacc[nt][2 * x], sacc[nt][2 * x + 1]));
            mt = fmaxf(mt, __shfl_xor_sync(0xffffffffu, mt, 1, 4));
            mt = fmaxf(mt, __shfl_xor_sync(0xffffffffu, mt, 2, 4));
            float m_new = fmaxf(m_run[x], mt);
            float alpha = ex2(m_run[x] - m_new);
            float lsum = 0.f;
            #pragma unroll
            for (int nt = 0; nt < 8; nt++) {
                float p0 = ex2(sacc[nt][2 * x]     - m_new);
                float p1 = ex2(sacc[nt][2 * x + 1] - m_new);
                sacc[nt][2 * x] = p0; sacc[nt][2 * x + 1] = p1;
                lsum += p0 + p1;
            }
            lsum += __shfl_xor_sync(0xffffffffu, lsum, 1, 4);
            lsum += __shfl_xor_sync(0xffffffffu, lsum, 2, 4);
            l_run[x] = l_run[x] * alpha + lsum;
            m_run[x] = m_new;
            #pragma unroll
            for (int nt = 0; nt < 8; nt++) {
                oacc[nt][2 * x]     *= alpha;
                oacc[nt][2 * x + 1] *= alpha;
            }
        }

        // ---- stage P (fp16) into warp-private strip ----
        #pragma unroll
        for (int nt = 0; nt < 8; nt++) {
            *(uint32_t*)&Pw[lr * TLD + nt * 8 + 2 * lc]       = pack_h2(sacc[nt][0], sacc[nt][1]);
            *(uint32_t*)&Pw[(lr + 8) * TLD + nt * 8 + 2 * lc] = pack_h2(sacc[nt][2], sacc[nt][3]);
        }
        __syncwarp();

        // ---- O += P V ----
        #pragma unroll
        for (int kcp = 0; kcp < 4; kcp++) {
            uint32_t a[4];
            ldsm_x4(a, pwb + (uint32_t)((a_row * TLD + kcp * 16 + a_col) * 2));
            #pragma unroll
            for (int dp = 0; dp < 4; dp++) {
                uint32_t vb[4];
                ldsm_x4_t(vb, vcur + (uint32_t)(((kcp * 16 + a_row) * TLD
                                                 + dp * 16 + a_col) * 2));
                mma_f16(oacc[2 * dp],     a, vb);
                mma_f16(oacc[2 * dp + 1], a, vb + 2);
            }
        }
    }
    #undef A_ISSUE

    // ---- finalize; write O fp16 in [B,N,C] layout ----
    const int b = bh >> 4, h = bh & 15;
    #pragma unroll
    for (int x = 0; x < 2; x++) {
        float inv = 1.f / l_run[x];
        int row = q0 + wid * 16 + lr + x * 8;
        __half* dst = Ob + ((size_t)(b * SEQ + row)) * DIMC + h * HD;
        #pragma unroll
        for (int nt = 0; nt < 8; nt++)
            *(uint32_t*)&dst[nt * 8 + 2 * lc] =
                pack_h2(oacc[nt][2 * x] * inv, oacc[nt][2 * x + 1] * inv);
    }
}

// ============================================================================
// Launcher
// ============================================================================
extern "C" void kernel_launch(void* const* d_in, const int* in_sizes, int n_in,
                              void* d_out, int out_size)
{
    const float* x     = (const float*)d_in[0];   // [2,2048,1024]
    const float* Wqkv  = (const float*)d_in[1];   // [3072,1024]
    const float* Wproj = (const float*)d_in[2];   // [1024,1024]
    const float* bproj = (const float*)d_in[3];   // [1024]
    float* out = (float*)d_out;

    __half *xh, *wqkvh, *wprojh, *Qb, *Kb, *Vb, *Oh;
    cudaGetSymbolAddress((void**)&xh,     g_xh);
    cudaGetSymbolAddress((void**)&wqkvh,  g_wqkvh);
    cudaGetSymbolAddress((void**)&wprojh, g_wprojh);
    cudaGetSymbolAddress((void**)&Qb, g_Q);
    cudaGetSymbolAddress((void**)&Kb, g_K);
    cudaGetSymbolAddress((void**)&Vb, g_V);
    cudaGetSymbolAddress((void**)&Oh, g_Oh);

    cudaFuncSetAttribute(gemm_h_kernel,
                         cudaFuncAttributeMaxDynamicSharedMemorySize, GEMM_SMEM);
    cudaFuncSetAttribute(attn_mma_kernel,
                         cudaFuncAttributeMaxDynamicSharedMemorySize, AT_SMEM);

    // 0) fp32 -> fp16 input conversion
    {
        int n4x = BATCH * SEQ * DIMC / 4;
        int n4q = 3 * DIMC * DIMC / 4;
        int n4p = DIMC * DIMC / 4;
        f2h_kernel<<<n4x / 256, 256>>>((const float4*)x,     (uint2*)xh,     n4x);
        f2h_kernel<<<n4q / 256, 256>>>((const float4*)Wqkv,  (uint2*)wqkvh,  n4q);
        f2h_kernel<<<n4p / 256, 256>>>((const float4*)Wproj, (uint2*)wprojh, n4p);
    }

    // 1) QKV projection; Q scaled by SCALE_Q*log2e for ex2 softmax
    dim3 g1(3 * DIMC / 128, (BATCH * SEQ) / 128);   // (24, 32)
    gemm_h_kernel<<<g1, 256, GEMM_SMEM>>>(xh, wqkvh, 0, Qb, Kb, Vb, nullptr, nullptr);

    // 2) flash attention -> fp16 O
    dim3 g2(SEQ / QT, BATCH * NH);                  // (16, 32)
    attn_mma_kernel<<<g2, 256, AT_SMEM>>>(Qb, Kb, Vb, Oh);

    // 3) output projection (fp16 in, fp32 out) + bias
    dim3 g3(DIMC / 128, (BATCH * SEQ) / 128);       // (8, 32)
    gemm_h_kernel<<<g3, 256, GEMM_SMEM>>>(Oh, wprojh, 1, nullptr, nullptr, nullptr,
                                          bproj, out);
}

// round 16
// speedup vs baseline: 1.1481x; 1.0792x over previous
#include <cuda_runtime.h>
#include <cuda_fp16.h>
#include <cstdint>

// ---------------- problem constants ----------------
#define DIMC  1024
#define NH    16
#define HD    64
#define SEQ   2048
#define BATCH 2
#define GK    1024
#define SCALE_Q 0.125f
#define QSCALE_L2E 0.180336880f     // SCALE_Q * log2(e)

// scratch (device globals; no runtime allocation)
__device__ __half g_xh[BATCH * SEQ * DIMC];      // x in fp16
__device__ __half g_wqkvh[3 * DIMC * DIMC];      // W_qkv fp16
__device__ __half g_wprojh[DIMC * DIMC];         // W_proj fp16
__device__ __half g_Q[BATCH * NH * SEQ * HD];    // [B,H,N,D] fp16, scaled by SCALE_Q*log2e
__device__ __half g_K[BATCH * NH * SEQ * HD];
__device__ __half g_V[BATCH * NH * SEQ * HD];
__device__ __half g_Oh[BATCH * SEQ * DIMC];      // attention out [B,N,C] fp16

__device__ __forceinline__ uint32_t smem_u32(const void* p) {
    uint32_t a;
    asm("{ .reg .u64 t; cvta.to.shared.u64 t, %1; cvt.u32.u64 %0, t; }"
        : "=r"(a) : "l"(p));
    return a;
}

__device__ __forceinline__ uint32_t pack_h2(float lo, float hi) {
    __half2 h = __floats2half2_rn(lo, hi);
    return *(uint32_t*)&h;
}

__device__ __forceinline__ float ex2(float x) {
    float y;
    asm("ex2.approx.f32 %0, %1;" : "=f"(y) : "f"(x));
    return y;
}

__device__ __forceinline__ void mma_f16(float* c, const uint32_t* a, const uint32_t* b) {
    asm volatile(
        "mma.sync.aligned.m16n8k16.row.col.f32.f16.f16.f32 "
        "{%0,%1,%2,%3}, {%4,%5,%6,%7}, {%8,%9}, {%0,%1,%2,%3};"
        : "+f"(c[0]), "+f"(c[1]), "+f"(c[2]), "+f"(c[3])
        : "r"(a[0]), "r"(a[1]), "r"(a[2]), "r"(a[3]), "r"(b[0]), "r"(b[1]));
}

__device__ __forceinline__ void ldsm_x4(uint32_t* r, uint32_t addr) {
    asm volatile("ldmatrix.sync.aligned.m8n8.x4.shared.b16 {%0,%1,%2,%3}, [%4];"
        : "=r"(r[0]), "=r"(r[1]), "=r"(r[2]), "=r"(r[3]) : "r"(addr));
}

__device__ __forceinline__ void ldsm_x4_t(uint32_t* r, uint32_t addr) {
    asm volatile("ldmatrix.sync.aligned.m8n8.x4.trans.shared.b16 {%0,%1,%2,%3}, [%4];"
        : "=r"(r[0]), "=r"(r[1]), "=r"(r[2]), "=r"(r[3]) : "r"(addr));
}

__device__ __forceinline__ void cp16(uint32_t dst, const void* src) {
    asm volatile("cp.async.cg.shared.global [%0], [%1], 16;"
        :: "r"(dst), "l"(src));
}
#define CP_COMMIT() asm volatile("cp.async.commit_group;" ::: "memory")

// ============================================================================
// fused fp32 -> fp16 convert for x, W_qkv, W_proj (one launch)
// ============================================================================
#define N4X (BATCH * SEQ * DIMC / 4)
#define N4Q (3 * DIMC * DIMC / 4)
#define N4P (DIMC * DIMC / 4)

__global__ __launch_bounds__(256) void f2h_all_kernel(
    const float4* __restrict__ x,  const float4* __restrict__ wq,
    const float4* __restrict__ wp, uint2* __restrict__ xh,
    uint2* __restrict__ wqh, uint2* __restrict__ wph)
{
    int i = blockIdx.x * blockDim.x + threadIdx.x;
    const float4* in;
    uint2* out;
    int j;
    if (i < N4X)              { in = x;  out = xh;  j = i; }
    else if (i < N4X + N4Q)   { in = wq; out = wqh; j = i - N4X; }
    else                      { in = wp; out = wph; j = i - N4X - N4Q; }
    float4 v = in[j];
    uint2 o;
    o.x = pack_h2(v.x, v.y);
    o.y = pack_h2(v.z, v.w);
    out[j] = o;
}

// ============================================================================
// TN GEMM, fp16 in, fp32 acc. CTA tile 64x128, K-chunk 32 halfs, 3-stage
// cp.async pipeline, ONE sync per chunk. 256 threads = 8 warps (2M x 4N),
// warp tile 32x32 (acc 32 regs) -> __launch_bounds__(256,3): 3 CTAs/SM.
// mode 0: QKV scatter (fp16 out, Q scaled by SCALE_Q*log2e); mode 1: fp32+bias.
// ============================================================================
#define ALD 40
#define A_ST (64 * ALD)                  // halfs: A tile 64 rows
#define STG (A_ST + 128 * ALD)           // + B tile 128 rows
#define GEMM_SMEM (3 * STG * 2)

__global__ __launch_bounds__(256, 3) void gemm_h_kernel(
    const __half* __restrict__ A, const __half* __restrict__ B, int mode,
    __half* __restrict__ Qb, __half* __restrict__ Kb, __half* __restrict__ Vb,
    const float* __restrict__ bias, float* __restrict__ Out)
{
    extern __shared__ __half smh[];
    const int tid = threadIdx.x, wid = tid >> 5, lane = tid & 31;
    const int n0 = blockIdx.x * 128, m0 = blockIdx.y * 64;
    const int wm = wid >> 2;            // 0..1 -> m offset 32*wm
    const int wn = wid & 3;             // 0..3 -> n offset 32*wn
    const int lr = lane >> 2, lc = lane & 3;
    const uint32_t sb = smem_u32(smh);

    const int f_row = lane & 15;
    const int f_col = (lane >> 4) << 3;

    const int crow = tid >> 2;          // 0..63
    const int cch  = (tid & 3) << 3;    // half offset 0,8,16,24

    const __half* Ag = A + (size_t)m0 * GK;
    const __half* Bg = B + (size_t)n0 * GK;

    float acc[2][4][4];
    #pragma unroll
    for (int mt = 0; mt < 2; mt++)
        #pragma unroll
        for (int nt = 0; nt < 4; nt++)
            #pragma unroll
            for (int j = 0; j < 4; j++) acc[mt][nt][j] = 0.f;

    const int NCHUNK = GK / 32;         // 32

    // issue chunk c into stage c%3: A 64 rows (1 cp16/thread), B 128 (2)
    #define G_ISSUE(c) do {                                                      \
        uint32_t ab = sb + (uint32_t)((c) % 3) * STG * 2;                        \
        uint32_t bb = ab + A_ST * 2;                                             \
        cp16(ab + (uint32_t)((crow * ALD + cch) * 2),                            \
             Ag + (size_t)crow * GK + (c) * 32 + cch);                           \
        _Pragma("unroll")                                                        \
        for (int i_ = 0; i_ < 2; i_++) {                                         \
            int row_ = crow + i_ * 64;                                           \
            cp16(bb + (uint32_t)((row_ * ALD + cch) * 2),                        \
                 Bg + (size_t)row_ * GK + (c) * 32 + cch);                       \
        }                                                                        \
        CP_COMMIT();                                                             \
    } while (0)

    G_ISSUE(0);
    G_ISSUE(1);

    for (int kt = 0; kt < NCHUNK; kt++) {
        if (kt + 1 < NCHUNK)
            asm volatile("cp.async.wait_group 1;" ::: "memory");
        else
            asm volatile("cp.async.wait_group 0;" ::: "memory");
        __syncthreads();
        if (kt + 2 < NCHUNK) G_ISSUE(kt + 2);   // overwrites stage of kt-1: safe

        const uint32_t abase = sb + (uint32_t)((kt % 3) * STG) * 2u;
        const uint32_t bbase = abase + A_ST * 2;
        #pragma unroll
        for (int ks = 0; ks < 2; ks++) {
            uint32_t afr[2][4], bfr[2][4];
            #pragma unroll
            for (int mt = 0; mt < 2; mt++)
                ldsm_x4(afr[mt],
                        abase + (uint32_t)(((wm * 32 + mt * 16 + f_row) * ALD
                                            + ks * 16 + f_col) * 2));
            #pragma unroll
            for (int p = 0; p < 2; p++)
                ldsm_x4(bfr[p],
                        bbase + (uint32_t)(((wn * 32 + p * 16 + f_row) * ALD
                                            + ks * 16 + f_col) * 2));
            #pragma unroll
            for (int mt = 0; mt < 2; mt++)
                #pragma unroll
                for (int nt = 0; nt < 4; nt++) {
                    uint32_t b2[2] = { bfr[nt >> 1][nt & 1], bfr[nt >> 1][2 + (nt & 1)] };
                    mma_f16(acc[mt][nt], afr[mt], b2);
                }
        }
    }
    #undef G_ISSUE

    #pragma unroll
    for (int mt = 0; mt < 2; mt++) {
        #pragma unroll
        for (int nt = 0; nt < 4; nt++) {
            #pragma unroll
            for (int half_ = 0; half_ < 2; half_++) {
                int row = m0 + wm * 32 + mt * 16 + lr + half_ * 8;
                int col = n0 + wn * 32 + nt * 8 + lc * 2;
                float vx = acc[mt][nt][half_ * 2 + 0];
                float vy = acc[mt][nt][half_ * 2 + 1];
                if (mode == 0) {
                    int b = row >> 11, n = row & 2047;
                    int t = col >> 10, h = (col >> 6) & 15, d = col & 63;
                    size_t dst = ((size_t)((b << 4) + h) * SEQ + n) * HD + d;
                    if (t == 0)     // fold log2(e) into Q so softmax can use ex2
                        *(uint32_t*)(Qb + dst) = pack_h2(vx * QSCALE_L2E, vy * QSCALE_L2E);
                    else if (t == 1)
                        *(uint32_t*)(Kb + dst) = pack_h2(vx, vy);
                    else
                        *(uint32_t*)(Vb + dst) = pack_h2(vx, vy);
                } else {
                    float2 bb = *(const float2*)(bias + col);
                    float2 v; v.x = vx + bb.x; v.y = vy + bb.y;
                    *(float2*)(Out + (size_t)row * DIMC + col) = v;
                }
            }
        }
    }
}

// ============================================================================
// Flash attention (validated R15): f16 mma + ldmatrix; 3-stage cp.async K/V
// pipeline, ONE __syncthreads per tile; ex2 softmax in log2-units.
// CTA: 128 q-rows of one (b,h); 8 warps x 16 rows. KV tile 64. O fp16 [B,N,C].
// ============================================================================
#define QT 128
#define KT 64
#define TLD 72
#define KBUF (KT * TLD)
#define KVSTG (2 * KBUF)
#define AT_SMEM ((3 * KVSTG + QT * TLD) * 2)

__global__ __launch_bounds__(256) void attn_mma_kernel(
    const __half* __restrict__ Qb, const __half* __restrict__ Kb,
    const __half* __restrict__ Vb, __half* __restrict__ Ob)
{
    extern __shared__ __half smh[];
    __half* Ps = smh + 3 * KVSTG;

    const int tid = threadIdx.x, wid = tid >> 5, lane = tid & 31;
    const int lr = lane >> 2, lc = lane & 3;
    const int bh = blockIdx.y;
    const int q0 = blockIdx.x * QT;
    const __half* Qp = Qb + (size_t)bh * SEQ * HD;
    const __half* Kp = Kb + (size_t)bh * SEQ * HD;
    const __half* Vp = Vb + (size_t)bh * SEQ * HD;

    const int a_row  = lane & 15;
    const int a_col  = (lane >> 4) << 3;
    const int s_row  = lane & 7;
    const int s_col  = (lane >> 3) << 3;

    const uint32_t sb = smem_u32(smh);

    const int crow = tid >> 3;
    const int cch  = (tid & 7) << 3;

    #define A_ISSUE(c) do {                                                      \
        uint32_t kb_ = sb + (uint32_t)((c) % 3) * KVSTG * 2;                     \
        uint32_t vb_ = kb_ + KBUF * 2;                                           \
        _Pragma("unroll")                                                        \
        for (int i_ = 0; i_ < 2; i_++) {                                         \
            int row_ = crow + i_ * 32;                                           \
            cp16(kb_ + (uint32_t)((row_ * TLD + cch) * 2),                       \
                 Kp + (size_t)((c) * KT + row_) * HD + cch);                     \
            cp16(vb_ + (uint32_t)((row_ * TLD + cch) * 2),                       \
                 Vp + (size_t)((c) * KT + row_) * HD + cch);                     \
        }                                                                        \
        CP_COMMIT();                                                             \
    } while (0)

    A_ISSUE(0);
    A_ISSUE(1);

    #pragma unroll
    for (int i = 0; i < 4; i++) {
        int f = tid + i * 256;
        int row = f >> 3, ch = (f & 7) << 3;
        *(uint4*)&Ps[row * TLD + ch] = *(const uint4*)&Qp[(size_t)(q0 + row) * HD + ch];
    }
    __syncthreads();

    uint32_t qf[4][4];
    {
        const uint32_t qwb = smem_u32(Ps + (wid * 16) * TLD);
        #pragma unroll
        for (int ks = 0; ks < 4; ks++)
            ldsm_x4(qf[ks], qwb + (uint32_t)((a_row * TLD + ks * 16 + a_col) * 2));
    }

    float m_run[2] = { -1e30f, -1e30f };
    float l_run[2] = { 0.f, 0.f };
    float oacc[8][4];
    #pragma unroll
    for (int nt = 0; nt < 8; nt++)
        #pragma unroll
        for (int j = 0; j < 4; j++) oacc[nt][j] = 0.f;

    __half* Pw = Ps + (wid * 16) * TLD;
    const uint32_t pwb = smem_u32(Pw);

    const int NT = SEQ / KT;
    for (int t = 0; t < NT; t++) {
        if (t + 1 < NT)
            asm volatile("cp.async.wait_group 1;" ::: "memory");
        else
            asm volatile("cp.async.wait_group 0;" ::: "memory");
        __syncthreads();
        if (t + 2 < NT) A_ISSUE(t + 2);

        const uint32_t kcur = sb + (uint32_t)((t % 3) * KVSTG) * 2u;
        const uint32_t vcur = kcur + KBUF * 2;

        float sacc[8][4];
        #pragma unroll
        for (int nt = 0; nt < 8; nt++)
            #pragma unroll
            for (int j = 0; j < 4; j++) sacc[nt][j] = 0.f;

        #pragma unroll
        for (int nt = 0; nt < 8; nt++) {
            #pragma unroll
            for (int ks = 0; ks < 2; ks++) {
                uint32_t kb[4];
                ldsm_x4(kb, kcur + (uint32_t)(((nt * 8 + s_row) * TLD
                                               + ks * 32 + s_col) * 2));
                mma_f16(sacc[nt], qf[2 * ks],     kb);
                mma_f16(sacc[nt], qf[2 * ks + 1], kb + 2);
            }
        }

        #pragma unroll
        for (int x = 0; x < 2; x++) {
            float mt = -1e30f;
            #pragma unroll
            for (int nt = 0; nt < 8; nt++)
                mt = fmaxf(mt, fmaxf(sacc[nt][2 * x], sacc[nt][2 * x + 1]));
            mt = fmaxf(mt, __shfl_xor_sync(0xffffffffu, mt, 1, 4));
            mt = fmaxf(mt, __shfl_xor_sync(0xffffffffu, mt, 2, 4));
            float m_new = fmaxf(m_run[x], mt);
            float alpha = ex2(m_run[x] - m_new);
            float lsum = 0.f;
            #pragma unroll
            for (int nt = 0; nt < 8; nt++) {
                float p0 = ex2(sacc[nt][2 * x]     - m_new);
                float p1 = ex2(sacc[nt][2 * x + 1] - m_new);
                sacc[nt][2 * x] = p0; sacc[nt][2 * x + 1] = p1;
                lsum += p0 + p1;
            }
            lsum += __shfl_xor_sync(0xffffffffu, lsum, 1, 4);
            lsum += __shfl_xor_sync(0xffffffffu, lsum, 2, 4);
            l_run[x] = l_run[x] * alpha + lsum;
            m_run[x] = m_new;
            #pragma unroll
            for (int nt = 0; nt < 8; nt++) {
                oacc[nt][2 * x]     *= alpha;
                oacc[nt][2 * x + 1] *= alpha;
            }
        }

        #pragma unroll
        for (int nt = 0; nt < 8; nt++) {
            *(uint32_t*)&Pw[lr * TLD + nt * 8 + 2 * lc]       = pack_h2(sacc[nt][0], sacc[nt][1]);
            *(uint32_t*)&Pw[(lr + 8) * TLD + nt * 8 + 2 * lc] = pack_h2(sacc[nt][2], sacc[nt][3]);
        }
        __syncwarp();

        #pragma unroll
        for (int kcp = 0; kcp < 4; kcp++) {
            uint32_t a[4];
            ldsm_x4(a, pwb + (uint32_t)((a_row * TLD + kcp * 16 + a_col) * 2));
            #pragma unroll
            for (int dp = 0; dp < 4; dp++) {
                uint32_t vb[4];
                ldsm_x4_t(vb, vcur + (uint32_t)(((kcp * 16 + a_row) * TLD
                                                 + dp * 16 + a_col) * 2));
                mma_f16(oacc[2 * dp],     a, vb);
                mma_f16(oacc[2 * dp + 1], a, vb + 2);
            }
        }
    }
    #undef A_ISSUE

    const int b = bh >> 4, h = bh & 15;
    #pragma unroll
    for (int x = 0; x < 2; x++) {
        float inv = 1.f / l_run[x];
        int row = q0 + wid * 16 + lr + x * 8;
        __half* dst = Ob + ((size_t)(b * SEQ + row)) * DIMC + h * HD;
        #pragma unroll
        for (int nt = 0; nt < 8; nt++)
            *(uint32_t*)&dst[nt * 8 + 2 * lc] =
                pack_h2(oacc[nt][2 * x] * inv, oacc[nt][2 * x + 1] * inv);
    }
}

// ============================================================================
// Launcher
// ============================================================================
extern "C" void kernel_launch(void* const* d_in, const int* in_sizes, int n_in,
                              void* d_out, int out_size)
{
    const float* x     = (const float*)d_in[0];   // [2,2048,1024]
    const float* Wqkv  = (const float*)d_in[1];   // [3072,1024]
    const float* Wproj = (const float*)d_in[2];   // [1024,1024]
    const float* bproj = (const float*)d_in[3];   // [1024]
    float* out = (float*)d_out;

    __half *xh, *wqkvh, *wprojh, *Qb, *Kb, *Vb, *Oh;
    cudaGetSymbolAddress((void**)&xh,     g_xh);
    cudaGetSymbolAddress((void**)&wqkvh,  g_wqkvh);
    cudaGetSymbolAddress((void**)&wprojh, g_wprojh);
    cudaGetSymbolAddress((void**)&Qb, g_Q);
    cudaGetSymbolAddress((void**)&Kb, g_K);
    cudaGetSymbolAddress((void**)&Vb, g_V);
    cudaGetSymbolAddress((void**)&Oh, g_Oh);

    cudaFuncSetAttribute(gemm_h_kernel,
                         cudaFuncAttributeMaxDynamicSharedMemorySize, GEMM_SMEM);
    cudaFuncSetAttribute(attn_mma_kernel,
                         cudaFuncAttributeMaxDynamicSharedMemorySize, AT_SMEM);

    // 0) fused fp32 -> fp16 input conversion (one launch)
    {
        int total = N4X + N4Q + N4P;               // 2097152
        f2h_all_kernel<<<total / 256, 256>>>(
            (const float4*)x, (const float4*)Wqkv, (const float4*)Wproj,
            (uint2*)xh, (uint2*)wqkvh, (uint2*)wprojh);
    }

    // 1) QKV projection; Q scaled by SCALE_Q*log2e for ex2 softmax
    dim3 g1(3 * DIMC / 128, (BATCH * SEQ) / 64);    // (24, 64)
    gemm_h_kernel<<<g1, 256, GEMM_SMEM>>>(xh, wqkvh, 0, Qb, Kb, Vb, nullptr, nullptr);

    // 2) flash attention -> fp16 O
    dim3 g2(SEQ / QT, BATCH * NH);                  // (16, 32)
    attn_mma_kernel<<<g2, 256, AT_SMEM>>>(Qb, Kb, Vb, Oh);

    // 3) output projection (fp16 in, fp32 out) + bias
    dim3 g3(DIMC / 128, (BATCH * SEQ) / 64);        // (8, 64)
    gemm_h_kernel<<<g3, 256, GEMM_SMEM>>>(Oh, wprojh, 1, nullptr, nullptr, nullptr,
                                          bproj, out);
}